// round 5
// baseline (speedup 1.0000x reference)
#include <cuda_runtime.h>
#include <math.h>

#define T_  128
#define B_  32
#define I_  128
#define H_  128
#define R_  100
#define O_  64
#define RH_ (R_*H_)       // 12800
#define COLS_ (H_*B_)     // 4096 (g*32+b) flat columns per region

typedef unsigned long long u64;

// Scratch (static device globals)
static __device__ float g_inp[(size_t)T_*R_*B_*H_];    // [T][R][b][g]
static __device__ float g_Hbr[(size_t)T_*B_*RH_];      // [T][b][r*H+g]  (for out_kernel)
static __device__ float g_Hkb[(size_t)T_*R_*COLS_];    // [T][r][g*32+b] (for phases)
static __device__ float g_msg[(size_t)R_*COLS_];       // [r][g*32+b]
static __device__ unsigned g_arrive;                   // grid-barrier counter

// ---- packed f32x2 helpers (sm_103a) ----
__device__ __forceinline__ u64 pk2(float lo, float hi){
    u64 r; asm("mov.b64 %0, {%1,%2};" : "=l"(r) : "f"(lo), "f"(hi)); return r;
}
__device__ __forceinline__ void up2(u64 v, float& lo, float& hi){
    asm("mov.b64 {%0,%1}, %2;" : "=f"(lo), "=f"(hi) : "l"(v));
}
__device__ __forceinline__ u64 fma2(u64 a, u64 b, u64 c){
    u64 d; asm("fma.rn.f32x2 %0, %1, %2, %3;" : "=l"(d) : "l"(a), "l"(b), "l"(c)); return d;
}

// ============================================================================
// Kernel 1: inp[t,r,b,g] = sum_i x[t,b,i]*W_ih[r,i,g] + bias[r,g]
// Also resets the grid-barrier counter.
// ============================================================================
__global__ __launch_bounds__(256) void inp_kernel(const float* __restrict__ x,
                                                  const float* __restrict__ W_ih,
                                                  const float* __restrict__ bias){
    if (blockIdx.x == 0 && blockIdx.y == 0 && threadIdx.x == 0) g_arrive = 0u;

    int r = blockIdx.x, t = blockIdx.y;
    __shared__ u64 xs[16][128];
    const float* xt = x + (size_t)t*B_*I_;
    for (int idx = threadIdx.x; idx < B_*I_; idx += 256){
        int b = idx >> 7, k = idx & 127;
        reinterpret_cast<float*>(&xs[b>>1][k])[b&1] = xt[idx];
    }
    __syncthreads();

    int gg = threadIdx.x & 63, quad = threadIdx.x >> 6;
    float bva = bias[r*H_ + gg], bvb = bias[r*H_ + gg + 64];
    u64 acc[8];
#pragma unroll
    for (int p=0;p<4;p++){ acc[p*2+0] = pk2(bva,bva); acc[p*2+1] = pk2(bvb,bvb); }

    const float* W = W_ih + (size_t)r*I_*H_;
#pragma unroll 4
    for (int k=0;k<I_;k++){
        float wa = W[(size_t)k*H_ + gg];
        float wb = W[(size_t)k*H_ + gg + 64];
        u64 wad = pk2(wa,wa), wbd = pk2(wb,wb);
#pragma unroll
        for (int p=0;p<4;p++){
            u64 xv = xs[quad*4+p][k];
            acc[p*2+0] = fma2(xv, wad, acc[p*2+0]);
            acc[p*2+1] = fma2(xv, wbd, acc[p*2+1]);
        }
    }
    float* op = g_inp + (size_t)(t*R_ + r)*B_*H_;
#pragma unroll
    for (int p=0;p<4;p++){
        int b0 = quad*8 + 2*p;
#pragma unroll
        for (int e=0;e<2;e++){
            float lo, hi; up2(acc[p*2+e], lo, hi);
            op[b0*H_     + gg + e*64] = lo;
            op[(b0+1)*H_ + gg + e*64] = hi;
        }
    }
}

// ============================================================================
// Persistent recurrent kernel: grid = 100 blocks x 1024 threads (1/SM by RF).
// Weights via LDG (L1-resident after first step); smem = C | hT | mT | Hs.
// ============================================================================
#define SM_C    0          // 10000 floats (40000 B)
#define SM_HT   10000      // 4096 floats [k*32+b]
#define SM_MT   14096      // 4096 floats
#define SM_HS   18192      // 6400 floats [i][c] strip for phase A
#define SM_FLOATS 24592    // 98368 bytes

__device__ __forceinline__ void gbar(unsigned target){
    __threadfence();
    __syncthreads();
    if (threadIdx.x == 0){
        atomicAdd(&g_arrive, 1u);
        volatile unsigned* va = &g_arrive;
        while (*va < target) { }
    }
    __syncthreads();
}

// phase A body: NJP j-pairs for one column c of a 64-col strip
template<int NJP>
__device__ __forceinline__ void msg_body(const float* __restrict__ Cs,
                                         const float* __restrict__ Hs,
                                         int c, int jp0, int col){
    u64 acc[NJP];
#pragma unroll
    for (int j=0;j<NJP;j++) acc[j] = 0ull;
#pragma unroll 2
    for (int i=0;i<R_;i++){
        float h = Hs[i*64 + c];
        u64 h2 = pk2(h, h);
        const float* Cr = Cs + i*R_ + jp0*2;
#pragma unroll
        for (int j=0;j<NJP;j++){
            u64 Cv = *reinterpret_cast<const u64*>(Cr + 2*j);   // {C[i,2j],C[i,2j+1]} bcast
            acc[j] = fma2(Cv, h2, acc[j]);
        }
    }
#pragma unroll
    for (int j=0;j<NJP;j++){
        float lo, hi; up2(acc[j], lo, hi);
        int jj = (jp0 + j)*2;
        __stcg(&g_msg[(size_t)jj*COLS_     + col], lo);
        __stcg(&g_msg[(size_t)(jj+1)*COLS_ + col], hi);
    }
}

__global__ __launch_bounds__(1024,1) void rnn_persist(const float* __restrict__ W_hh,
                                                      const float* __restrict__ W_rhh,
                                                      const float* __restrict__ C,
                                                      int t0, int t1, unsigned bars0){
    extern __shared__ float sm[];
    float* Cs = sm + SM_C;
    float* hT = sm + SM_HT;
    float* mT = sm + SM_MT;
    float* Hs = sm + SM_HS;

    const int r = blockIdx.x, tid = threadIdx.x;

    // stage connectome once per chunk
    {
        const float4* c4 = reinterpret_cast<const float4*>(C);
        float4* dc = reinterpret_cast<float4*>(Cs);
        for (int i=tid;i<2500;i+=1024) dc[i]=c4[i];
    }

    // phase-B mapping: lane = b, warp owns g-range [warp*4, warp*4+4)
    const int b  = tid & 31;
    const int g0 = (tid >> 5) * 4;
    // phase-A mapping: c = column within strip, jg -> j-pair group
    const int c  = tid & 63;
    const int jg = tid >> 6;                       // 0..15
    const int jp0 = (jg<2)? jg*4 : 8 + (jg-2)*3;   // 2x4 + 14x3 = 50 pairs

    // weight row base (ulonglong2 pairs), stride 32 u2 per k
    const ulonglong2* w1p = reinterpret_cast<const ulonglong2*>(W_hh  + (size_t)r*H_*H_ + g0);
    const ulonglong2* w2p = reinterpret_cast<const ulonglong2*>(W_rhh + (size_t)r*H_*H_ + g0);

    unsigned bars = bars0;

    for (int t = t0; t < t1; t++){
        if (t > 0){
            // stage hT (all blocks) — H[t-1] is final; overlaps phase A
            {
                const float4* Hp4 = reinterpret_cast<const float4*>(
                    g_Hkb + ((size_t)(t-1)*R_ + r)*COLS_);
                reinterpret_cast<float4*>(hT)[tid] = __ldcg(Hp4 + tid);
            }
            // phase A: blocks 0..63 compute a 64-col msg strip
            const int col0 = r*64;
            if (r < 64){
                const float* Hp = g_Hkb + (size_t)(t-1)*R_*COLS_ + col0;
                float4* Hs4 = reinterpret_cast<float4*>(Hs);
                for (int idx=tid; idx<1600; idx+=1024){
                    int i = idx >> 4, c4i = idx & 15;
                    Hs4[idx] = __ldcg(reinterpret_cast<const float4*>(Hp + (size_t)i*COLS_) + c4i);
                }
            }
            __syncthreads();
            if (r < 64){
                if (jg < 2) msg_body<4>(Cs, Hs, c, jp0, col0 + c);
                else        msg_body<3>(Cs, Hs, c, jp0, col0 + c);
            }
            gbar(++bars * (unsigned)R_);
            // stage mT (msg now ready)
            {
                const float4* Mp4 = reinterpret_cast<const float4*>(g_msg + (size_t)r*COLS_);
                reinterpret_cast<float4*>(mT)[tid] = __ldcg(Mp4 + tid);
            }
            __syncthreads();
        }

        // ---------------- phase B ----------------
        u64 acc0, acc1;
        {
            const float4 iv = __ldcg(reinterpret_cast<const float4*>(
                g_inp + ((size_t)t*R_ + r)*B_*H_ + b*H_ + g0));
            acc0 = pk2(iv.x, iv.y);
            acc1 = pk2(iv.z, iv.w);
        }
        if (t > 0){
#pragma unroll 4
            for (int k=0;k<H_;k++){
                ulonglong2 W1 = w1p[(size_t)k*32];     // 16B broadcast, L1-resident
                ulonglong2 W2 = w2p[(size_t)k*32];
                float h = hT[k*32 + b];
                float m = mT[k*32 + b];
                u64 h2 = pk2(h,h), m2 = pk2(m,m);
                acc0 = fma2(W1.x, h2, acc0);
                acc1 = fma2(W1.y, h2, acc1);
                acc0 = fma2(W2.x, m2, acc0);
                acc1 = fma2(W2.y, m2, acc1);
            }
        }
        {
            float v0,v1,v2,v3;
            up2(acc0, v0, v1); up2(acc1, v2, v3);
            float t0v = tanhf(v0), t1v = tanhf(v1), t2v = tanhf(v2), t3v = tanhf(v3);
            // g_Hbr[b][r*128+g0..] : one STG.128
            float4 o4 = make_float4(t0v, t1v, t2v, t3v);
            __stcg(reinterpret_cast<float4*>(
                g_Hbr + (size_t)t*B_*RH_ + (size_t)b*RH_ + r*H_ + g0), o4);
            // g_Hkb[r][(g)*32+b] : 4 coalesced scalars
            float* Hkb = g_Hkb + ((size_t)t*R_ + r)*COLS_ + b;
            __stcg(Hkb + (g0+0)*32, t0v);
            __stcg(Hkb + (g0+1)*32, t1v);
            __stcg(Hkb + (g0+2)*32, t2v);
            __stcg(Hkb + (g0+3)*32, t3v);
        }
        if (t < t1-1) gbar(++bars * (unsigned)R_);
    }
}

// ============================================================================
// Kernel 3: out[t,b,o] = H[t][b][:] @ W_out + b_out   grid (T,2), 128 thr
// ============================================================================
__global__ __launch_bounds__(128) void out_kernel(const float* __restrict__ W_out,
                                                  const float* __restrict__ b_out,
                                                  float* __restrict__ out){
    int t = blockIdx.x, bh = blockIdx.y;
    __shared__ u64 hsh[128][9];
    int tid = threadIdx.x;
    int og = tid & 15, rp = tid >> 4;
    int o0 = og*4;
    u64 acc[4];
    {
        const u64* bo = reinterpret_cast<const u64*>(b_out + o0);
        acc[0]=bo[0]; acc[1]=bo[1]; acc[2]=bo[0]; acc[3]=bo[1];
    }
    const float* Hb = g_Hbr + (size_t)t*B_*RH_ + (size_t)(bh*16)*RH_;
    for (int kt=0; kt<RH_/128; kt++){
        __syncthreads();
        for (int idx = tid; idx < 16*128; idx += 128){
            int b = idx >> 7, kk = idx & 127;
            reinterpret_cast<float*>(&hsh[kk][b>>1])[b&1] = Hb[(size_t)b*RH_ + kt*128 + kk];
        }
        __syncthreads();
#pragma unroll 4
        for (int kk=0; kk<128; kk++){
            int k = kt*128 + kk;
            ulonglong2 w = *reinterpret_cast<const ulonglong2*>(W_out + (size_t)k*O_ + o0);
            u64 hp = hsh[kk][rp];
            float h0, h1; up2(hp, h0, h1);
            u64 h0d = pk2(h0,h0), h1d = pk2(h1,h1);
            acc[0] = fma2(w.x, h0d, acc[0]);  acc[1] = fma2(w.y, h0d, acc[1]);
            acc[2] = fma2(w.x, h1d, acc[2]);  acc[3] = fma2(w.y, h1d, acc[3]);
        }
    }
    u64* op = reinterpret_cast<u64*>(out);
    int row0 = bh*16 + rp*2;
    size_t base0 = ((size_t)(t*B_ + row0  )*O_ + o0) >> 1;
    size_t base1 = ((size_t)(t*B_ + row0+1)*O_ + o0) >> 1;
    op[base0] = acc[0];  op[base0+1] = acc[1];
    op[base1] = acc[2];  op[base1+1] = acc[3];
}

// ============================================================================
// Launch: inp, 4x persistent chunks of 32 steps, out.
// ============================================================================
extern "C" void kernel_launch(void* const* d_in, const int* in_sizes, int n_in,
                              void* d_out, int out_size){
    const float* x     = (const float*)d_in[0];
    const float* C     = (const float*)d_in[1];
    const float* W_ih  = (const float*)d_in[2];
    const float* W_hh  = (const float*)d_in[3];
    const float* W_rhh = (const float*)d_in[4];
    const float* bias  = (const float*)d_in[5];
    const float* W_out = (const float*)d_in[6];
    const float* b_out = (const float*)d_in[7];
    float* out = (float*)d_out;

    cudaFuncSetAttribute(rnn_persist, cudaFuncAttributeMaxDynamicSharedMemorySize,
                         SM_FLOATS * (int)sizeof(float));

    inp_kernel<<<dim3(R_, T_), 256>>>(x, W_ih, bias);     // resets g_arrive

    // barriers before launch L: L0=0, then +62, +63, +63
    unsigned bars0[4] = {0u, 62u, 125u, 188u};
    for (int L = 0; L < 4; L++){
        rnn_persist<<<R_, 1024, SM_FLOATS * sizeof(float)>>>(
            W_hh, W_rhh, C, L*32, L*32 + 32, bars0[L]);
    }

    out_kernel<<<dim3(T_, 2), 128>>>(W_out, b_out, out);
}

// round 6
// speedup vs baseline: 1.1691x; 1.1691x over previous
#include <cuda_runtime.h>
#include <math.h>

#define T_  128
#define B_  32
#define I_  128
#define H_  128
#define R_  100
#define O_  64
#define RH_ (R_*H_)       // 12800
#define COLS_ (H_*B_)     // 4096 (g*32+b) flat columns per region

typedef unsigned long long u64;

// Scratch (static device globals)
static __device__ float g_inp[(size_t)T_*R_*B_*H_];    // [T][R][b][g]
static __device__ float g_Hbr[(size_t)T_*B_*RH_];      // [T][b][r*H+g]  (for out_kernel)
static __device__ float g_Hkb[(size_t)T_*R_*COLS_];    // [T][r][g*32+b] (for phases)
static __device__ float g_msg[(size_t)R_*COLS_];       // [r][g*32+b]
static __device__ unsigned g_arrive;                   // grid-barrier counter

// ---- packed f32x2 helpers (sm_103a) ----
__device__ __forceinline__ u64 pk2(float lo, float hi){
    u64 r; asm("mov.b64 %0, {%1,%2};" : "=l"(r) : "f"(lo), "f"(hi)); return r;
}
__device__ __forceinline__ void up2(u64 v, float& lo, float& hi){
    asm("mov.b64 {%0,%1}, %2;" : "=f"(lo), "=f"(hi) : "l"(v));
}
__device__ __forceinline__ u64 fma2(u64 a, u64 b, u64 c){
    u64 d; asm("fma.rn.f32x2 %0, %1, %2, %3;" : "=l"(d) : "l"(a), "l"(b), "l"(c)); return d;
}

// ============================================================================
// Kernel 1: inp[t,r,b,g] = sum_i x[t,b,i]*W_ih[r,i,g] + bias[r,g]
// Also resets the grid-barrier counter.
// ============================================================================
__global__ __launch_bounds__(256) void inp_kernel(const float* __restrict__ x,
                                                  const float* __restrict__ W_ih,
                                                  const float* __restrict__ bias){
    if (blockIdx.x == 0 && blockIdx.y == 0 && threadIdx.x == 0) g_arrive = 0u;

    int r = blockIdx.x, t = blockIdx.y;
    __shared__ u64 xs[16][128];
    const float* xt = x + (size_t)t*B_*I_;
    for (int idx = threadIdx.x; idx < B_*I_; idx += 256){
        int b = idx >> 7, k = idx & 127;
        reinterpret_cast<float*>(&xs[b>>1][k])[b&1] = xt[idx];
    }
    __syncthreads();

    int gg = threadIdx.x & 63, quad = threadIdx.x >> 6;
    float bva = bias[r*H_ + gg], bvb = bias[r*H_ + gg + 64];
    u64 acc[8];
#pragma unroll
    for (int p=0;p<4;p++){ acc[p*2+0] = pk2(bva,bva); acc[p*2+1] = pk2(bvb,bvb); }

    const float* W = W_ih + (size_t)r*I_*H_;
#pragma unroll 4
    for (int k=0;k<I_;k++){
        float wa = W[(size_t)k*H_ + gg];
        float wb = W[(size_t)k*H_ + gg + 64];
        u64 wad = pk2(wa,wa), wbd = pk2(wb,wb);
#pragma unroll
        for (int p=0;p<4;p++){
            u64 xv = xs[quad*4+p][k];
            acc[p*2+0] = fma2(xv, wad, acc[p*2+0]);
            acc[p*2+1] = fma2(xv, wbd, acc[p*2+1]);
        }
    }
    float* op = g_inp + (size_t)(t*R_ + r)*B_*H_;
#pragma unroll
    for (int p=0;p<4;p++){
        int b0 = quad*8 + 2*p;
#pragma unroll
        for (int e=0;e<2;e++){
            float lo, hi; up2(acc[p*2+e], lo, hi);
            op[b0*H_     + gg + e*64] = lo;
            op[(b0+1)*H_ + gg + e*64] = hi;
        }
    }
}

// ============================================================================
// Persistent recurrent kernel: grid = 100 blocks x 512 threads (1/SM by smem).
// smem (floats): W1[16384] | W2[16384] | C[10000] | overlay(12288):
//   phase A: Hs[100*44]   phase B: hT2(u64[4096]) + mT[4096]
// ============================================================================
#define SM_W1   0
#define SM_W2   16384
#define SM_C    32768
#define SM_OVL  42768
#define SM_MT   (SM_OVL + 8192)
#define SM_FLOATS (SM_MT + 4096)      // 55152? -> 50960+4096 = 55056 floats

__device__ __forceinline__ void gbar(unsigned target){
    __threadfence();
    __syncthreads();
    if (threadIdx.x == 0){
        atomicAdd(&g_arrive, 1u);
        volatile unsigned* va = &g_arrive;
        while (*va < target) { }
    }
    __syncthreads();
}

// phase A body: NJP j-pairs for one column
template<int NJP>
__device__ __forceinline__ void msg_body(const float* __restrict__ Cs,
                                         const float* __restrict__ Hs,
                                         int col, int jp0, int colg){
    u64 acc[NJP];
#pragma unroll
    for (int j=0;j<NJP;j++) acc[j] = 0ull;
#pragma unroll 2
    for (int i=0;i<R_;i++){
        float h = Hs[i*44 + col];
        u64 h2 = pk2(h, h);
        const float* Cr = Cs + i*R_ + jp0*2;
#pragma unroll
        for (int j=0;j<NJP;j++){
            u64 Cv = *reinterpret_cast<const u64*>(Cr + 2*j);   // {C[i,2j],C[i,2j+1]}
            acc[j] = fma2(Cv, h2, acc[j]);
        }
    }
#pragma unroll
    for (int j=0;j<NJP;j++){
        float lo, hi; up2(acc[j], lo, hi);
        int jj = (jp0 + j)*2;
        __stcg(&g_msg[(size_t)jj*COLS_     + colg], lo);
        __stcg(&g_msg[(size_t)(jj+1)*COLS_ + colg], hi);
    }
}

__global__ __launch_bounds__(512,1) void rnn_persist(const float* __restrict__ W_hh,
                                                     const float* __restrict__ W_rhh,
                                                     const float* __restrict__ C,
                                                     int t0, int t1, unsigned bars0){
    extern __shared__ float sm[];
    float* w1s = sm + SM_W1;
    float* w2s = sm + SM_W2;
    float* Cs  = sm + SM_C;
    float* Hs  = sm + SM_OVL;                      // phase A
    u64*   hT2 = reinterpret_cast<u64*>(sm + SM_OVL);  // phase B splat {h,h}
    float* mT  = sm + SM_MT;                       // phase B

    const int r = blockIdx.x, tid = threadIdx.x;

    // one-time staging: W1, W2, C
    {
        const float4* a  = reinterpret_cast<const float4*>(W_hh  + (size_t)r*H_*H_);
        const float4* bb = reinterpret_cast<const float4*>(W_rhh + (size_t)r*H_*H_);
        float4* d1 = reinterpret_cast<float4*>(w1s);
        float4* d2 = reinterpret_cast<float4*>(w2s);
        for (int i=tid;i<4096;i+=512){ d1[i]=a[i]; d2[i]=bb[i]; }
        const float4* c4 = reinterpret_cast<const float4*>(C);
        float4* dc = reinterpret_cast<float4*>(Cs);
        for (int i=tid;i<2500;i+=512) dc[i]=c4[i];
    }

    // phase-B mapping: bp (b-pair) and g-quad
    const int b0 = (tid & 15) * 2;
    const int g0 = (tid >> 4) * 4;
    // phase-A mapping: strip of ncols columns; thread -> (col, jg)
    const int col0  = (r < 96) ? r*41 : 3936 + (r-96)*40;
    const int ncols = (r < 96) ? 41 : 40;
    const int col = tid % 41;
    const int jg  = tid / 41;                     // 0..12
    const int jp0 = (jg < 2) ? jg*5 : 10 + (jg-2)*4;
    const bool a_act = (jg < 12) && (col < ncols);

    unsigned bars = bars0;

    for (int t = t0; t < t1; t++){
        if (t > 0){
            // ---------------- phase A ----------------
            {
                const float* Hbase = g_Hkb + (size_t)(t-1)*R_*COLS_ + col0;
                for (int idx = tid; idx < 100*41; idx += 512){
                    int i = idx / 41, cc = idx % 41;
                    if (cc < ncols)
                        Hs[i*44 + cc] = __ldcg(Hbase + (size_t)i*COLS_ + cc);
                }
            }
            __syncthreads();
            if (a_act){
                if (jg < 2) msg_body<5>(Cs, Hs, col, jp0, col0 + col);
                else        msg_body<4>(Cs, Hs, col, jp0, col0 + col);
            }
            gbar(++bars * (unsigned)R_);
        }

        // ---------------- phase B ----------------
        u64 acc00, acc01, acc10, acc11;      // {g0,g1}/{g2,g3} x {b0,b1}
        {
            const float* ip = g_inp + ((size_t)t*R_ + r)*B_*H_;
            float4 iv0 = __ldcg(reinterpret_cast<const float4*>(ip + b0*H_ + g0));
            float4 iv1 = __ldcg(reinterpret_cast<const float4*>(ip + (b0+1)*H_ + g0));
            acc00 = pk2(iv0.x, iv0.y);  acc10 = pk2(iv0.z, iv0.w);
            acc01 = pk2(iv1.x, iv1.y);  acc11 = pk2(iv1.z, iv1.w);
        }
        if (t > 0){
            // stage hT2 (splatted) and mT
            {
                const float4* Hp4 = reinterpret_cast<const float4*>(
                    g_Hkb + ((size_t)(t-1)*R_ + r)*COLS_);
                const float4* Mp4 = reinterpret_cast<const float4*>(g_msg + (size_t)r*COLS_);
                float4* hT2f = reinterpret_cast<float4*>(hT2);
                float4* mT4  = reinterpret_cast<float4*>(mT);
#pragma unroll
                for (int it=0; it<2; it++){
                    int i4 = tid + it*512;
                    float4 h4 = __ldcg(Hp4 + i4);
                    hT2f[2*i4+0] = make_float4(h4.x, h4.x, h4.y, h4.y);
                    hT2f[2*i4+1] = make_float4(h4.z, h4.z, h4.w, h4.w);
                    mT4[i4] = __ldcg(Mp4 + i4);
                }
            }
            __syncthreads();
#pragma unroll 4
            for (int k=0;k<H_;k++){
                ulonglong2 w1 = *reinterpret_cast<const ulonglong2*>(w1s + k*H_ + g0);
                ulonglong2 w2 = *reinterpret_cast<const ulonglong2*>(w2s + k*H_ + g0);
                ulonglong2 hp = *reinterpret_cast<const ulonglong2*>(hT2 + k*32 + b0);
                float2 mp = *reinterpret_cast<const float2*>(mT + k*32 + b0);
                u64 m0d = pk2(mp.x, mp.x), m1d = pk2(mp.y, mp.y);
                acc00 = fma2(w1.x, hp.x, acc00);  acc00 = fma2(w2.x, m0d, acc00);
                acc01 = fma2(w1.x, hp.y, acc01);  acc01 = fma2(w2.x, m1d, acc01);
                acc10 = fma2(w1.y, hp.x, acc10);  acc10 = fma2(w2.y, m0d, acc10);
                acc11 = fma2(w1.y, hp.y, acc11);  acc11 = fma2(w2.y, m1d, acc11);
            }
            __syncthreads();   // overlay free for next phase A
        }
        {
            float d00,d01,d02,d03, d10,d11,d12,d13;
            up2(acc00, d00, d01);  up2(acc10, d02, d03);
            up2(acc01, d10, d11);  up2(acc11, d12, d13);
            float t00=tanhf(d00), t01=tanhf(d01), t02=tanhf(d02), t03=tanhf(d03);
            float t10=tanhf(d10), t11=tanhf(d11), t12=tanhf(d12), t13=tanhf(d13);
            float* Hbr = g_Hbr + (size_t)t*B_*RH_ + (size_t)r*H_;
            __stcg(reinterpret_cast<float4*>(Hbr + (size_t)b0*RH_ + g0),
                   make_float4(t00,t01,t02,t03));
            __stcg(reinterpret_cast<float4*>(Hbr + (size_t)(b0+1)*RH_ + g0),
                   make_float4(t10,t11,t12,t13));
            float* Hkb = g_Hkb + ((size_t)t*R_ + r)*COLS_;
            __stcg(reinterpret_cast<float2*>(Hkb + (g0+0)*32 + b0), make_float2(t00,t10));
            __stcg(reinterpret_cast<float2*>(Hkb + (g0+1)*32 + b0), make_float2(t01,t11));
            __stcg(reinterpret_cast<float2*>(Hkb + (g0+2)*32 + b0), make_float2(t02,t12));
            __stcg(reinterpret_cast<float2*>(Hkb + (g0+3)*32 + b0), make_float2(t03,t13));
        }
        if (t < t1-1) gbar(++bars * (unsigned)R_);
    }
}

// ============================================================================
// Kernel 3: out[t,b,o] = H[t][b][:] @ W_out + b_out   grid (T,2), 128 thr
// ============================================================================
__global__ __launch_bounds__(128) void out_kernel(const float* __restrict__ W_out,
                                                  const float* __restrict__ b_out,
                                                  float* __restrict__ out){
    int t = blockIdx.x, bh = blockIdx.y;
    __shared__ u64 hsh[128][9];
    int tid = threadIdx.x;
    int og = tid & 15, rp = tid >> 4;
    int o0 = og*4;
    u64 acc[4];
    {
        const u64* bo = reinterpret_cast<const u64*>(b_out + o0);
        acc[0]=bo[0]; acc[1]=bo[1]; acc[2]=bo[0]; acc[3]=bo[1];
    }
    const float* Hb = g_Hbr + (size_t)t*B_*RH_ + (size_t)(bh*16)*RH_;
    for (int kt=0; kt<RH_/128; kt++){
        __syncthreads();
        for (int idx = tid; idx < 16*128; idx += 128){
            int b = idx >> 7, kk = idx & 127;
            reinterpret_cast<float*>(&hsh[kk][b>>1])[b&1] = Hb[(size_t)b*RH_ + kt*128 + kk];
        }
        __syncthreads();
#pragma unroll 4
        for (int kk=0; kk<128; kk++){
            int k = kt*128 + kk;
            ulonglong2 w = *reinterpret_cast<const ulonglong2*>(W_out + (size_t)k*O_ + o0);
            u64 hp = hsh[kk][rp];
            float h0, h1; up2(hp, h0, h1);
            u64 h0d = pk2(h0,h0), h1d = pk2(h1,h1);
            acc[0] = fma2(w.x, h0d, acc[0]);  acc[1] = fma2(w.y, h0d, acc[1]);
            acc[2] = fma2(w.x, h1d, acc[2]);  acc[3] = fma2(w.y, h1d, acc[3]);
        }
    }
    u64* op = reinterpret_cast<u64*>(out);
    int row0 = bh*16 + rp*2;
    size_t base0 = ((size_t)(t*B_ + row0  )*O_ + o0) >> 1;
    size_t base1 = ((size_t)(t*B_ + row0+1)*O_ + o0) >> 1;
    op[base0] = acc[0];  op[base0+1] = acc[1];
    op[base1] = acc[2];  op[base1+1] = acc[3];
}

// ============================================================================
// Launch: inp, 4x persistent chunks of 32 steps, out.
// ============================================================================
extern "C" void kernel_launch(void* const* d_in, const int* in_sizes, int n_in,
                              void* d_out, int out_size){
    const float* x     = (const float*)d_in[0];
    const float* C     = (const float*)d_in[1];
    const float* W_ih  = (const float*)d_in[2];
    const float* W_hh  = (const float*)d_in[3];
    const float* W_rhh = (const float*)d_in[4];
    const float* bias  = (const float*)d_in[5];
    const float* W_out = (const float*)d_in[6];
    const float* b_out = (const float*)d_in[7];
    float* out = (float*)d_out;

    cudaFuncSetAttribute(rnn_persist, cudaFuncAttributeMaxDynamicSharedMemorySize,
                         SM_FLOATS * (int)sizeof(float));

    inp_kernel<<<dim3(R_, T_), 256>>>(x, W_ih, bias);     // resets g_arrive

    // barriers before launch L: chunk0 consumes 62, others 63
    unsigned bars0[4] = {0u, 62u, 125u, 188u};
    for (int L = 0; L < 4; L++){
        rnn_persist<<<R_, 512, SM_FLOATS * sizeof(float)>>>(
            W_hh, W_rhh, C, L*32, L*32 + 32, bars0[L]);
    }

    out_kernel<<<dim3(T_, 2), 128>>>(W_out, b_out, out);
}